// round 4
// baseline (speedup 1.0000x reference)
#include <cuda_runtime.h>
#include <cuda_fp16.h>
#include <math.h>

#define Bv 2
#define Cv 256
#define Hv 96
#define Wv 192
#define Gv 4
#define Kv 9
#define GC (Cv / Gv)      // 64 channels per group
#define HW (Hv * Wv)      // 18432

// NHWC half scratch (allocation-free: __device__ globals). ~18.9MB each.
__device__ __half g_right_nhwc[(size_t)Bv * Hv * Wv * Cv];
__device__ __half g_left_nhwc[(size_t)Bv * Hv * Wv * Cv];

static __device__ __forceinline__ __half2 u32_as_h2(unsigned int u) {
    __half2 h;
    *reinterpret_cast<unsigned int*>(&h) = u;
    return h;
}
static __device__ __forceinline__ unsigned int h2_as_u32(__half2 h) {
    return *reinterpret_cast<unsigned int*>(&h);
}

// ---------------------------------------------------------------------------
// NCHW fp32 -> NHWC fp16 transpose+convert.
// Tile: 64 channels x 192 w (full row). Block 256.
// Reads: float4 along W (12 per thread). Smem: half tile [64][200] (pad 8).
// Writes: uint4 (8 halves) per (w, seg), coalesced 128B per w.
// grid: (C/64, 2*B*H)  [y >= B*H selects left]
// ---------------------------------------------------------------------------
#define TP_PITCH 200   // halves per smem row (192 + 8 pad)
__global__ __launch_bounds__(256) void nchw_to_nhwc_half_kernel(
    const float* __restrict__ right_in, const float* __restrict__ left_in)
{
    __shared__ __half tile[64 * TP_PITCH];
    const int tid = threadIdx.x;
    int z = blockIdx.y;
    int is_left = (z >= Bv * Hv);
    int bh = is_left ? (z - Bv * Hv) : z;
    int b = bh / Hv;
    int h = bh % Hv;
    const float* in = is_left ? left_in : right_in;
    __half* out = is_left ? g_left_nhwc : g_right_nhwc;

    const int c0 = blockIdx.x * 64;
    const float* src = in + (size_t)b * Cv * HW + (size_t)c0 * HW + (size_t)h * Wv;

    // 64 rows x 48 float4 = 3072 float4 loads; 12 per thread
#pragma unroll
    for (int i = 0; i < 12; i++) {
        int idx = tid + i * 256;          // 0..3071
        int c = idx / 48;
        int w4 = idx - c * 48;            // float4 index along W
        float4 v = *reinterpret_cast<const float4*>(src + (size_t)c * HW + w4 * 4);
        __half hv[4];
        hv[0] = __float2half(v.x);
        hv[1] = __float2half(v.y);
        hv[2] = __float2half(v.z);
        hv[3] = __float2half(v.w);
        *reinterpret_cast<uint2*>(&tile[c * TP_PITCH + w4 * 4]) =
            *reinterpret_cast<uint2*>(hv);
    }
    __syncthreads();

    // 192 w x 8 segs = 1536 uint4 stores; 6 per thread
    const int seg = tid & 7;              // 8-channel segment
    const int wb = tid >> 3;              // 0..31
#pragma unroll
    for (int i = 0; i < 6; i++) {
        int w = wb + i * 32;
        __half hv[8];
#pragma unroll
        for (int j = 0; j < 8; j++)
            hv[j] = tile[(seg * 8 + j) * TP_PITCH + w];
        __half* dst = out + ((size_t)bh * Wv + w) * Cv + c0 + seg * 8;
        *reinterpret_cast<uint4*>(dst) = *reinterpret_cast<uint4*>(hv);
    }
}

// ---------------------------------------------------------------------------
// Correlation kernel. 256-thread block = 4x2 pixel tile, 32 threads/pixel.
// Phase 1: 72 threads precompute (pixel,k) gather offsets + splatted half2
//          weights into smem.
// Phase 2: software-pipelined k-loop (gathers for k+1 in flight while
//          blending k); 4-corner blend in HFMA2, dot in fp32, 8-lane shfl
//          reduction per group.
// grid: (W/4, H/2, B)
// ---------------------------------------------------------------------------
__global__ __launch_bounds__(256, 4) void corr_kernel(
    const float* __restrict__ flow,
    const float* __restrict__ extra,
    float* __restrict__ out)
{
    __shared__ int4  s_off[8 * Kv];
    __shared__ uint4 s_wgt[8 * Kv];

    const int tid = threadIdx.x;
    const int b = blockIdx.z;

    if (tid < 8 * Kv) {
        const int pi = tid / Kv;
        const int k = tid - pi * Kv;
        const int w = blockIdx.x * 4 + (pi & 3);
        const int h = blockIdx.y * 2 + (pi >> 2);
        const int pix = h * Wv + w;

        const float fx = flow[(size_t)(b * 2 + 0) * HW + pix];
        const float fy = flow[(size_t)(b * 2 + 1) * HW + pix];
        const float ex = extra[((size_t)(b * Kv + k) * 2 + 0) * HW + pix];
        const float ey = extra[((size_t)(b * Kv + k) * 2 + 1) * HW + pix];
        const float x = (float)w + fx + (float)(k - 4) + ex;
        const float y = (float)h + fy + ey;

        const float x0f = floorf(x);
        const float y0f = floorf(y);
        const int ix0 = (int)x0f;
        const int iy0 = (int)y0f;
        const float wx1 = x - x0f;
        const float wy1 = y - y0f;
        const float wx0 = 1.0f - wx1;
        const float wy0 = 1.0f - wy1;

        const bool vx0 = (ix0 >= 0) && (ix0 <= Wv - 1);
        const bool vx1 = (ix0 + 1 >= 0) && (ix0 + 1 <= Wv - 1);
        const bool vy0 = (iy0 >= 0) && (iy0 <= Hv - 1);
        const bool vy1 = (iy0 + 1 >= 0) && (iy0 + 1 <= Hv - 1);

        const int cx0 = min(max(ix0, 0), Wv - 1);
        const int cx1 = min(max(ix0 + 1, 0), Wv - 1);
        const int cy0 = min(max(iy0, 0), Hv - 1);
        const int cy1 = min(max(iy0 + 1, 0), Hv - 1);

        const float w00 = (vx0 && vy0) ? (wx0 * wy0) : 0.0f;
        const float w01 = (vx1 && vy0) ? (wx1 * wy0) : 0.0f;
        const float w10 = (vx0 && vy1) ? (wx0 * wy1) : 0.0f;
        const float w11 = (vx1 && vy1) ? (wx1 * wy1) : 0.0f;

        s_off[tid] = make_int4((cy0 * Wv + cx0) * Cv,
                               (cy0 * Wv + cx1) * Cv,
                               (cy1 * Wv + cx0) * Cv,
                               (cy1 * Wv + cx1) * Cv);
        s_wgt[tid] = make_uint4(h2_as_u32(__float2half2_rn(w00)),
                                h2_as_u32(__float2half2_rn(w01)),
                                h2_as_u32(__float2half2_rn(w10)),
                                h2_as_u32(__float2half2_rn(w11)));
    }
    __syncthreads();

    const int lane = tid & 31;
    const int p = tid >> 5;                  // 0..7 pixel in tile
    const int w = blockIdx.x * 4 + (p & 3);
    const int h = blockIdx.y * 2 + (p >> 2);
    const int pix = h * Wv + w;

    // left vector (8 channels) -> fp32
    const __half* lptr = g_left_nhwc + ((size_t)(b * Hv + h) * Wv + w) * Cv + lane * 8;
    uint4 Lu = *reinterpret_cast<const uint4*>(lptr);
    float Lf[8];
    {
        const __half2* lh = (const __half2*)&Lu;
#pragma unroll
        for (int i = 0; i < 4; i++) {
            float2 f = __half22float2(lh[i]);
            Lf[2 * i] = f.x;
            Lf[2 * i + 1] = f.y;
        }
    }

    const __half* rbase = g_right_nhwc + (size_t)b * HW * Cv + lane * 8;

    // ---- software pipeline: stage k=0 ----
    uint4 wg_cur = s_wgt[p * Kv];
    uint4 a0, a1, a2, a3;
    {
        const int4 off = s_off[p * Kv];
        a0 = *reinterpret_cast<const uint4*>(rbase + off.x);
        a1 = *reinterpret_cast<const uint4*>(rbase + off.y);
        a2 = *reinterpret_cast<const uint4*>(rbase + off.z);
        a3 = *reinterpret_cast<const uint4*>(rbase + off.w);
    }

#pragma unroll
    for (int k = 0; k < Kv; k++) {
        uint4 b0, b1, b2, b3, wg_nxt;
        if (k < Kv - 1) {
            const int4 off = s_off[p * Kv + k + 1];
            wg_nxt = s_wgt[p * Kv + k + 1];
            b0 = *reinterpret_cast<const uint4*>(rbase + off.x);
            b1 = *reinterpret_cast<const uint4*>(rbase + off.y);
            b2 = *reinterpret_cast<const uint4*>(rbase + off.z);
            b3 = *reinterpret_cast<const uint4*>(rbase + off.w);
        }

        const __half2 w00 = u32_as_h2(wg_cur.x);
        const __half2 w01 = u32_as_h2(wg_cur.y);
        const __half2 w10 = u32_as_h2(wg_cur.z);
        const __half2 w11 = u32_as_h2(wg_cur.w);

        const __half2* pa = (const __half2*)&a0;
        const __half2* pc = (const __half2*)&a1;
        const __half2* pd = (const __half2*)&a2;
        const __half2* pe = (const __half2*)&a3;

        float s0 = 0.0f, s1 = 0.0f;
#pragma unroll
        for (int j = 0; j < 4; j++) {
            __half2 v = __hmul2(w00, pa[j]);
            v = __hfma2(w01, pc[j], v);
            v = __hfma2(w10, pd[j], v);
            v = __hfma2(w11, pe[j], v);
            float2 f = __half22float2(v);
            s0 = fmaf(Lf[2 * j], f.x, s0);
            s1 = fmaf(Lf[2 * j + 1], f.y, s1);
        }
        float s = s0 + s1;

        // reduce across the 8 threads of this channel-group (contiguous lanes)
        s += __shfl_xor_sync(0xffffffffu, s, 4);
        s += __shfl_xor_sync(0xffffffffu, s, 2);
        s += __shfl_xor_sync(0xffffffffu, s, 1);

        if ((lane & 7) == 0) {
            const int g = lane >> 3;  // 0..3
            out[((size_t)(b * Gv + g) * Kv + k) * HW + pix] = s * (1.0f / GC);
        }

        if (k < Kv - 1) {
            a0 = b0; a1 = b1; a2 = b2; a3 = b3;
            wg_cur = wg_nxt;
        }
    }
}

extern "C" void kernel_launch(void* const* d_in, const int* in_sizes, int n_in,
                              void* d_out, int out_size) {
    const float* left  = (const float*)d_in[0];
    const float* right = (const float*)d_in[1];
    const float* flow  = (const float*)d_in[2];
    const float* extra = (const float*)d_in[3];
    float* out = (float*)d_out;

    {
        dim3 grid(Cv / 64, 2 * Bv * Hv);
        nchw_to_nhwc_half_kernel<<<grid, 256>>>(right, left);
    }
    {
        dim3 grid(Wv / 4, Hv / 2, Bv);
        corr_kernel<<<grid, 256>>>(flow, extra, out);
    }
}

// round 5
// speedup vs baseline: 1.1124x; 1.1124x over previous
#include <cuda_runtime.h>
#include <cuda_fp16.h>
#include <math.h>

#define Bv 2
#define Cv 256
#define Hv 96
#define Wv 192
#define Gv 4
#define Kv 9
#define GC (Cv / Gv)      // 64 channels per group
#define HW (Hv * Wv)      // 18432

// NHWC half scratch for RIGHT feature only (~18.9MB).
__device__ __half g_right_nhwc[(size_t)Bv * Hv * Wv * Cv];

static __device__ __forceinline__ __half2 u32_as_h2(unsigned int u) {
    __half2 h;
    *reinterpret_cast<unsigned int*>(&h) = u;
    return h;
}
static __device__ __forceinline__ unsigned int h2_as_u32(__half2 h) {
    return *reinterpret_cast<unsigned int*>(&h);
}

// ---------------------------------------------------------------------------
// NCHW fp32 -> NHWC fp16 transpose+convert (right feature only).
// Tile: 64 channels x 32 w. grid: (W/32, C/64, B*H), block: 256.
// Stores are uint4 (8 halves) per thread.
// ---------------------------------------------------------------------------
__global__ __launch_bounds__(256) void nchw_to_nhwc_half_kernel(
    const float* __restrict__ right_in)
{
    __shared__ float tile[64][33];
    const int tid = threadIdx.x;
    const int bh = blockIdx.z;
    const int b = bh / Hv;
    const int h = bh % Hv;

    const float* src = right_in + (size_t)b * Cv * HW + (size_t)h * Wv;
    const int w0 = blockIdx.x * 32;
    const int c0 = blockIdx.y * 64;
    const int tx = tid & 31;
    const int ty = tid >> 5;
#pragma unroll
    for (int i = 0; i < 8; i++) {
        int c = ty + i * 8;
        tile[c][tx] = src[(size_t)(c0 + c) * HW + (w0 + tx)];
    }
    __syncthreads();

    const int r = tid >> 3;        // 0..31  (w within tile)
    const int seg = tid & 7;       // 0..7   (8-channel segment)
    __half hv[8];
#pragma unroll
    for (int j = 0; j < 8; j++)
        hv[j] = __float2half(tile[seg * 8 + j][r]);
    __half* dst = g_right_nhwc + ((size_t)bh * Wv + (w0 + r)) * Cv + c0 + seg * 8;
    *reinterpret_cast<uint4*>(dst) = *reinterpret_cast<uint4*>(hv);
}

// ---------------------------------------------------------------------------
// Correlation kernel. 256-thread block = 4x2 pixel tile, 32 threads/pixel.
// Phase 0: stage left (NCHW fp32) into smem — thread = channel, float4 over
//          the 4-wide w-span, 2 rows.
// Phase 1: 72 threads precompute (pixel,k) gather offsets + splatted half2
//          weights into smem.
// Phase 2: lane owns 8 channels; 4-corner blend in HFMA2, dot in fp32,
//          8-lane shfl reduction per group.
// grid: (W/4, H/2, B)
// ---------------------------------------------------------------------------
__global__ __launch_bounds__(256) void corr_kernel(
    const float* __restrict__ left,
    const float* __restrict__ flow,
    const float* __restrict__ extra,
    float* __restrict__ out)
{
    __shared__ float s_left[8][Cv];    // [pixel][channel], 8KB
    __shared__ int4  s_off[8 * Kv];
    __shared__ uint4 s_wgt[8 * Kv];

    const int tid = threadIdx.x;
    const int b = blockIdx.z;
    const int w0 = blockIdx.x * 4;
    const int h0 = blockIdx.y * 2;

    // ---- Phase 0: left staging (all 256 threads; thread = channel) ----
    {
        const float* lsrc = left + ((size_t)b * Cv + tid) * HW;
#pragma unroll
        for (int row = 0; row < 2; row++) {
            float4 v = *reinterpret_cast<const float4*>(lsrc + (h0 + row) * Wv + w0);
            s_left[row * 4 + 0][tid] = v.x;
            s_left[row * 4 + 1][tid] = v.y;
            s_left[row * 4 + 2][tid] = v.z;
            s_left[row * 4 + 3][tid] = v.w;
        }
    }

    // ---- Phase 1: coordinate precompute (72 threads) ----
    if (tid < 8 * Kv) {
        const int pi = tid / Kv;
        const int k = tid - pi * Kv;
        const int w = w0 + (pi & 3);
        const int h = h0 + (pi >> 2);
        const int pix = h * Wv + w;

        const float fx = flow[(size_t)(b * 2 + 0) * HW + pix];
        const float fy = flow[(size_t)(b * 2 + 1) * HW + pix];
        const float ex = extra[((size_t)(b * Kv + k) * 2 + 0) * HW + pix];
        const float ey = extra[((size_t)(b * Kv + k) * 2 + 1) * HW + pix];
        const float x = (float)w + fx + (float)(k - 4) + ex;
        const float y = (float)h + fy + ey;

        const float x0f = floorf(x);
        const float y0f = floorf(y);
        const int ix0 = (int)x0f;
        const int iy0 = (int)y0f;
        const float wx1 = x - x0f;
        const float wy1 = y - y0f;
        const float wx0 = 1.0f - wx1;
        const float wy0 = 1.0f - wy1;

        const bool vx0 = (ix0 >= 0) && (ix0 <= Wv - 1);
        const bool vx1 = (ix0 + 1 >= 0) && (ix0 + 1 <= Wv - 1);
        const bool vy0 = (iy0 >= 0) && (iy0 <= Hv - 1);
        const bool vy1 = (iy0 + 1 >= 0) && (iy0 + 1 <= Hv - 1);

        const int cx0 = min(max(ix0, 0), Wv - 1);
        const int cx1 = min(max(ix0 + 1, 0), Wv - 1);
        const int cy0 = min(max(iy0, 0), Hv - 1);
        const int cy1 = min(max(iy0 + 1, 0), Hv - 1);

        const float w00 = (vx0 && vy0) ? (wx0 * wy0) : 0.0f;
        const float w01 = (vx1 && vy0) ? (wx1 * wy0) : 0.0f;
        const float w10 = (vx0 && vy1) ? (wx0 * wy1) : 0.0f;
        const float w11 = (vx1 && vy1) ? (wx1 * wy1) : 0.0f;

        s_off[tid] = make_int4((cy0 * Wv + cx0) * Cv,
                               (cy0 * Wv + cx1) * Cv,
                               (cy1 * Wv + cx0) * Cv,
                               (cy1 * Wv + cx1) * Cv);
        s_wgt[tid] = make_uint4(h2_as_u32(__float2half2_rn(w00)),
                                h2_as_u32(__float2half2_rn(w01)),
                                h2_as_u32(__float2half2_rn(w10)),
                                h2_as_u32(__float2half2_rn(w11)));
    }
    __syncthreads();

    // ---- Phase 2: gather + correlate ----
    const int lane = tid & 31;
    const int p = tid >> 5;                  // 0..7 pixel in tile
    const int w = w0 + (p & 3);
    const int h = h0 + (p >> 2);
    const int pix = h * Wv + w;

    float Lf[8];
    {
        const float4* lp = (const float4*)&s_left[p][lane * 8];
        float4 A = lp[0], B = lp[1];
        Lf[0] = A.x; Lf[1] = A.y; Lf[2] = A.z; Lf[3] = A.w;
        Lf[4] = B.x; Lf[5] = B.y; Lf[6] = B.z; Lf[7] = B.w;
    }

    const __half* rbase = g_right_nhwc + (size_t)b * HW * Cv + lane * 8;

#pragma unroll
    for (int k = 0; k < Kv; k++) {
        const int4 off = s_off[p * Kv + k];
        const uint4 wg = s_wgt[p * Kv + k];
        const __half2 w00 = u32_as_h2(wg.x);
        const __half2 w01 = u32_as_h2(wg.y);
        const __half2 w10 = u32_as_h2(wg.z);
        const __half2 w11 = u32_as_h2(wg.w);

        const uint4 g00 = *reinterpret_cast<const uint4*>(rbase + off.x);
        const uint4 g01 = *reinterpret_cast<const uint4*>(rbase + off.y);
        const uint4 g10 = *reinterpret_cast<const uint4*>(rbase + off.z);
        const uint4 g11 = *reinterpret_cast<const uint4*>(rbase + off.w);

        const __half2* pa = (const __half2*)&g00;
        const __half2* pc = (const __half2*)&g01;
        const __half2* pd = (const __half2*)&g10;
        const __half2* pe = (const __half2*)&g11;

        float s0 = 0.0f, s1 = 0.0f;
#pragma unroll
        for (int j = 0; j < 4; j++) {
            __half2 v = __hmul2(w00, pa[j]);
            v = __hfma2(w01, pc[j], v);
            v = __hfma2(w10, pd[j], v);
            v = __hfma2(w11, pe[j], v);
            float2 f = __half22float2(v);
            s0 = fmaf(Lf[2 * j], f.x, s0);
            s1 = fmaf(Lf[2 * j + 1], f.y, s1);
        }
        float s = s0 + s1;

        // reduce across the 8 threads of this channel-group (contiguous lanes)
        s += __shfl_xor_sync(0xffffffffu, s, 4);
        s += __shfl_xor_sync(0xffffffffu, s, 2);
        s += __shfl_xor_sync(0xffffffffu, s, 1);

        if ((lane & 7) == 0) {
            const int g = lane >> 3;  // 0..3
            out[((size_t)(b * Gv + g) * Kv + k) * HW + pix] = s * (1.0f / GC);
        }
    }
}

extern "C" void kernel_launch(void* const* d_in, const int* in_sizes, int n_in,
                              void* d_out, int out_size) {
    const float* left  = (const float*)d_in[0];
    const float* right = (const float*)d_in[1];
    const float* flow  = (const float*)d_in[2];
    const float* extra = (const float*)d_in[3];
    float* out = (float*)d_out;

    {
        dim3 grid(Wv / 32, Cv / 64, Bv * Hv);
        nchw_to_nhwc_half_kernel<<<grid, 256>>>(right);
    }
    {
        dim3 grid(Wv / 4, Hv / 2, Bv);
        corr_kernel<<<grid, 256>>>(left, flow, extra, out);
    }
}

// round 6
// speedup vs baseline: 1.1473x; 1.0314x over previous
#include <cuda_runtime.h>
#include <cuda_fp16.h>
#include <math.h>

#define Bv 2
#define Cv 256
#define Hv 96
#define Wv 192
#define Gv 4
#define Kv 9
#define GC (Cv / Gv)      // 64 channels per group
#define HW (Hv * Wv)      // 18432
#define LPITCH 260        // padded left-tile pitch (floats) for conflict-free STS

// NHWC half scratch for RIGHT feature only (~18.9MB).
__device__ __half g_right_nhwc[(size_t)Bv * Hv * Wv * Cv];

static __device__ __forceinline__ __half2 u32_as_h2(unsigned int u) {
    __half2 h;
    *reinterpret_cast<unsigned int*>(&h) = u;
    return h;
}
static __device__ __forceinline__ unsigned int h2_as_u32(__half2 h) {
    return *reinterpret_cast<unsigned int*>(&h);
}

// ---------------------------------------------------------------------------
// NCHW fp32 -> NHWC fp16 transpose+convert (right feature only).
// Tile: 64 channels x 32 w. grid: (W/32, C/64, B*H), block: 256.
// Stores are uint4 (8 halves) per thread.
// ---------------------------------------------------------------------------
__global__ __launch_bounds__(256) void nchw_to_nhwc_half_kernel(
    const float* __restrict__ right_in)
{
    __shared__ float tile[64][33];
    const int tid = threadIdx.x;
    const int bh = blockIdx.z;
    const int b = bh / Hv;
    const int h = bh % Hv;

    const float* src = right_in + (size_t)b * Cv * HW + (size_t)h * Wv;
    const int w0 = blockIdx.x * 32;
    const int c0 = blockIdx.y * 64;
    const int tx = tid & 31;
    const int ty = tid >> 5;
#pragma unroll
    for (int i = 0; i < 8; i++) {
        int c = ty + i * 8;
        tile[c][tx] = src[(size_t)(c0 + c) * HW + (w0 + tx)];
    }
    __syncthreads();

    const int r = tid >> 3;        // 0..31  (w within tile)
    const int seg = tid & 7;       // 0..7   (8-channel segment)
    __half hv[8];
#pragma unroll
    for (int j = 0; j < 8; j++)
        hv[j] = __float2half(tile[seg * 8 + j][r]);
    __half* dst = g_right_nhwc + ((size_t)bh * Wv + (w0 + r)) * Cv + c0 + seg * 8;
    *reinterpret_cast<uint4*>(dst) = *reinterpret_cast<uint4*>(hv);
}

// ---------------------------------------------------------------------------
// Correlation kernel. 256-thread block = 4x2 pixel tile, 32 threads/pixel.
// Phase 0: stage left (NCHW fp32) into smem with COALESCED mapping:
//          thread = (pixel p = tid&7, channel c = tid>>3 + 32*i). Lanes
//          sharing a channel read the tile's 8 pixels (2 rows x 4 floats) ->
//          ~2-3 wavefronts per warp-load instead of 32.
// Phase 1: 72 threads precompute (pixel,k) gather offsets + splatted half2
//          weights into smem.
// Phase 2: lane owns 8 channels; 4-corner blend in HFMA2, dot in fp32,
//          8-lane shfl reduction per group.
// grid: (W/4, H/2, B)
// ---------------------------------------------------------------------------
__global__ __launch_bounds__(256) void corr_kernel(
    const float* __restrict__ left,
    const float* __restrict__ flow,
    const float* __restrict__ extra,
    float* __restrict__ out)
{
    __shared__ float s_left[8 * LPITCH]; // [pixel][channel] pitch-padded, ~8.3KB
    __shared__ int4  s_off[8 * Kv];
    __shared__ uint4 s_wgt[8 * Kv];

    const int tid = threadIdx.x;
    const int b = blockIdx.z;
    const int w0 = blockIdx.x * 4;
    const int h0 = blockIdx.y * 2;

    // ---- Phase 0: coalesced left staging ----
    {
        const int p = tid & 7;            // pixel in tile
        const int cb = tid >> 3;          // 0..31 channel base
        const int lw = w0 + (p & 3);
        const int lh = h0 + (p >> 2);
        const float* lp = left + (size_t)b * Cv * HW + (size_t)lh * Wv + lw;
#pragma unroll
        for (int i = 0; i < 8; i++) {
            const int c = cb + i * 32;
            s_left[p * LPITCH + c] = lp[(size_t)c * HW];
        }
    }

    // ---- Phase 1: coordinate precompute (72 threads) ----
    if (tid < 8 * Kv) {
        const int pi = tid / Kv;
        const int k = tid - pi * Kv;
        const int w = w0 + (pi & 3);
        const int h = h0 + (pi >> 2);
        const int pix = h * Wv + w;

        const float fx = flow[(size_t)(b * 2 + 0) * HW + pix];
        const float fy = flow[(size_t)(b * 2 + 1) * HW + pix];
        const float ex = extra[((size_t)(b * Kv + k) * 2 + 0) * HW + pix];
        const float ey = extra[((size_t)(b * Kv + k) * 2 + 1) * HW + pix];
        const float x = (float)w + fx + (float)(k - 4) + ex;
        const float y = (float)h + fy + ey;

        const float x0f = floorf(x);
        const float y0f = floorf(y);
        const int ix0 = (int)x0f;
        const int iy0 = (int)y0f;
        const float wx1 = x - x0f;
        const float wy1 = y - y0f;
        const float wx0 = 1.0f - wx1;
        const float wy0 = 1.0f - wy1;

        const bool vx0 = (ix0 >= 0) && (ix0 <= Wv - 1);
        const bool vx1 = (ix0 + 1 >= 0) && (ix0 + 1 <= Wv - 1);
        const bool vy0 = (iy0 >= 0) && (iy0 <= Hv - 1);
        const bool vy1 = (iy0 + 1 >= 0) && (iy0 + 1 <= Hv - 1);

        const int cx0 = min(max(ix0, 0), Wv - 1);
        const int cx1 = min(max(ix0 + 1, 0), Wv - 1);
        const int cy0 = min(max(iy0, 0), Hv - 1);
        const int cy1 = min(max(iy0 + 1, 0), Hv - 1);

        const float w00 = (vx0 && vy0) ? (wx0 * wy0) : 0.0f;
        const float w01 = (vx1 && vy0) ? (wx1 * wy0) : 0.0f;
        const float w10 = (vx0 && vy1) ? (wx0 * wy1) : 0.0f;
        const float w11 = (vx1 && vy1) ? (wx1 * wy1) : 0.0f;

        s_off[tid] = make_int4((cy0 * Wv + cx0) * Cv,
                               (cy0 * Wv + cx1) * Cv,
                               (cy1 * Wv + cx0) * Cv,
                               (cy1 * Wv + cx1) * Cv);
        s_wgt[tid] = make_uint4(h2_as_u32(__float2half2_rn(w00)),
                                h2_as_u32(__float2half2_rn(w01)),
                                h2_as_u32(__float2half2_rn(w10)),
                                h2_as_u32(__float2half2_rn(w11)));
    }
    __syncthreads();

    // ---- Phase 2: gather + correlate ----
    const int lane = tid & 31;
    const int p = tid >> 5;                  // 0..7 pixel in tile
    const int w = w0 + (p & 3);
    const int h = h0 + (p >> 2);
    const int pix = h * Wv + w;

    float Lf[8];
    {
        const float4* lp = (const float4*)&s_left[p * LPITCH + lane * 8];
        float4 A = lp[0], B = lp[1];
        Lf[0] = A.x; Lf[1] = A.y; Lf[2] = A.z; Lf[3] = A.w;
        Lf[4] = B.x; Lf[5] = B.y; Lf[6] = B.z; Lf[7] = B.w;
    }

    const __half* rbase = g_right_nhwc + (size_t)b * HW * Cv + lane * 8;

#pragma unroll
    for (int k = 0; k < Kv; k++) {
        const int4 off = s_off[p * Kv + k];
        const uint4 wg = s_wgt[p * Kv + k];
        const __half2 w00 = u32_as_h2(wg.x);
        const __half2 w01 = u32_as_h2(wg.y);
        const __half2 w10 = u32_as_h2(wg.z);
        const __half2 w11 = u32_as_h2(wg.w);

        const uint4 g00 = *reinterpret_cast<const uint4*>(rbase + off.x);
        const uint4 g01 = *reinterpret_cast<const uint4*>(rbase + off.y);
        const uint4 g10 = *reinterpret_cast<const uint4*>(rbase + off.z);
        const uint4 g11 = *reinterpret_cast<const uint4*>(rbase + off.w);

        const __half2* pa = (const __half2*)&g00;
        const __half2* pc = (const __half2*)&g01;
        const __half2* pd = (const __half2*)&g10;
        const __half2* pe = (const __half2*)&g11;

        float s0 = 0.0f, s1 = 0.0f;
#pragma unroll
        for (int j = 0; j < 4; j++) {
            __half2 v = __hmul2(w00, pa[j]);
            v = __hfma2(w01, pc[j], v);
            v = __hfma2(w10, pd[j], v);
            v = __hfma2(w11, pe[j], v);
            float2 f = __half22float2(v);
            s0 = fmaf(Lf[2 * j], f.x, s0);
            s1 = fmaf(Lf[2 * j + 1], f.y, s1);
        }
        float s = s0 + s1;

        // reduce across the 8 threads of this channel-group (contiguous lanes)
        s += __shfl_xor_sync(0xffffffffu, s, 4);
        s += __shfl_xor_sync(0xffffffffu, s, 2);
        s += __shfl_xor_sync(0xffffffffu, s, 1);

        if ((lane & 7) == 0) {
            const int g = lane >> 3;  // 0..3
            out[((size_t)(b * Gv + g) * Kv + k) * HW + pix] = s * (1.0f / GC);
        }
    }
}

extern "C" void kernel_launch(void* const* d_in, const int* in_sizes, int n_in,
                              void* d_out, int out_size) {
    const float* left  = (const float*)d_in[0];
    const float* right = (const float*)d_in[1];
    const float* flow  = (const float*)d_in[2];
    const float* extra = (const float*)d_in[3];
    float* out = (float*)d_out;

    {
        dim3 grid(Wv / 32, Cv / 64, Bv * Hv);
        nchw_to_nhwc_half_kernel<<<grid, 256>>>(right);
    }
    {
        dim3 grid(Wv / 4, Hv / 2, Bv);
        corr_kernel<<<grid, 256>>>(left, flow, extra, out);
    }
}

// round 8
// speedup vs baseline: 1.1970x; 1.0433x over previous
#include <cuda_runtime.h>
#include <cuda_fp16.h>
#include <math.h>

#define Bv 2
#define Cv 256
#define Hv 96
#define Wv 192
#define Gv 4
#define Kv 9
#define GC (Cv / Gv)      // 64 channels per group
#define HW (Hv * Wv)      // 18432
#define TPX 16            // pixels per corr block (16 x 1 tile)
#define LPITCH 260        // padded left-tile pitch; multiple of 4 => float4-aligned rows

// NHWC half scratch for RIGHT feature only (~18.9MB).
__device__ __half g_right_nhwc[(size_t)Bv * Hv * Wv * Cv];

static __device__ __forceinline__ __half2 u32_as_h2(unsigned int u) {
    __half2 h;
    *reinterpret_cast<unsigned int*>(&h) = u;
    return h;
}
static __device__ __forceinline__ unsigned int h2_as_u32(__half2 h) {
    return *reinterpret_cast<unsigned int*>(&h);
}

// ---------------------------------------------------------------------------
// NCHW fp32 -> NHWC fp16 transpose+convert (right feature only).
// Tile: 64 channels x 32 w. grid: (W/32, C/64, B*H), block: 256.
// ---------------------------------------------------------------------------
__global__ __launch_bounds__(256) void nchw_to_nhwc_half_kernel(
    const float* __restrict__ right_in)
{
    __shared__ float tile[64][33];
    const int tid = threadIdx.x;
    const int bh = blockIdx.z;
    const int b = bh / Hv;
    const int h = bh % Hv;

    const float* src = right_in + (size_t)b * Cv * HW + (size_t)h * Wv;
    const int w0 = blockIdx.x * 32;
    const int c0 = blockIdx.y * 64;
    const int tx = tid & 31;
    const int ty = tid >> 5;
#pragma unroll
    for (int i = 0; i < 8; i++) {
        int c = ty + i * 8;
        tile[c][tx] = src[(size_t)(c0 + c) * HW + (w0 + tx)];
    }
    __syncthreads();

    const int r = tid >> 3;        // 0..31  (w within tile)
    const int seg = tid & 7;       // 0..7   (8-channel segment)
    __half hv[8];
#pragma unroll
    for (int j = 0; j < 8; j++)
        hv[j] = __float2half(tile[seg * 8 + j][r]);
    __half* dst = g_right_nhwc + ((size_t)bh * Wv + (w0 + r)) * Cv + c0 + seg * 8;
    *reinterpret_cast<uint4*>(dst) = *reinterpret_cast<uint4*>(hv);
}

// ---------------------------------------------------------------------------
// Correlation kernel. 512-thread block = 16x1 pixel tile, warp = pixel.
// Phase 0: stage left (NCHW fp32): 256 channels x 1 row x 16 px -> 256 L1
//          lines per block (16 wf/pixel), near-conflict-free smem scatter.
// Phase 1: 144 threads precompute (pixel,k) gather offsets + half2 weights.
// Phase 2: lane owns 8 channels; 4-corner HFMA2 blend, fp32 dot, 8-lane
//          shfl reduction per group.
// grid: (W/16, H, B)
// ---------------------------------------------------------------------------
__global__ __launch_bounds__(512) void corr_kernel(
    const float* __restrict__ left,
    const float* __restrict__ flow,
    const float* __restrict__ extra,
    float* __restrict__ out)
{
    __shared__ float s_left[TPX * LPITCH];   // ~16.6KB
    __shared__ int4  s_off[TPX * Kv];        // 2.25KB
    __shared__ uint4 s_wgt[TPX * Kv];        // 2.25KB

    const int tid = threadIdx.x;
    const int b = blockIdx.z;
    const int w0 = blockIdx.x * TPX;
    const int h0 = blockIdx.y;

    // ---- Phase 0: left staging (512 threads; 8 channels each) ----
    {
        const int p = tid & 15;           // pixel in tile
        const int cb = tid >> 4;          // 0..31 channel base
        const float* lp = left + (size_t)b * Cv * HW + (size_t)h0 * Wv + (w0 + p);
#pragma unroll
        for (int i = 0; i < 8; i++) {
            const int c = cb + i * 32;
            s_left[p * LPITCH + c] = lp[(size_t)c * HW];
        }
    }

    // ---- Phase 1: coordinate precompute (144 threads) ----
    if (tid < TPX * Kv) {
        const int pi = tid / Kv;
        const int k = tid - pi * Kv;
        const int w = w0 + pi;
        const int pix = h0 * Wv + w;

        const float fx = flow[(size_t)(b * 2 + 0) * HW + pix];
        const float fy = flow[(size_t)(b * 2 + 1) * HW + pix];
        const float ex = extra[((size_t)(b * Kv + k) * 2 + 0) * HW + pix];
        const float ey = extra[((size_t)(b * Kv + k) * 2 + 1) * HW + pix];
        const float x = (float)w + fx + (float)(k - 4) + ex;
        const float y = (float)h0 + fy + ey;

        const float x0f = floorf(x);
        const float y0f = floorf(y);
        const int ix0 = (int)x0f;
        const int iy0 = (int)y0f;
        const float wx1 = x - x0f;
        const float wy1 = y - y0f;
        const float wx0 = 1.0f - wx1;
        const float wy0 = 1.0f - wy1;

        const bool vx0 = (ix0 >= 0) && (ix0 <= Wv - 1);
        const bool vx1 = (ix0 + 1 >= 0) && (ix0 + 1 <= Wv - 1);
        const bool vy0 = (iy0 >= 0) && (iy0 <= Hv - 1);
        const bool vy1 = (iy0 + 1 >= 0) && (iy0 + 1 <= Hv - 1);

        const int cx0 = min(max(ix0, 0), Wv - 1);
        const int cx1 = min(max(ix0 + 1, 0), Wv - 1);
        const int cy0 = min(max(iy0, 0), Hv - 1);
        const int cy1 = min(max(iy0 + 1, 0), Hv - 1);

        const float w00 = (vx0 && vy0) ? (wx0 * wy0) : 0.0f;
        const float w01 = (vx1 && vy0) ? (wx1 * wy0) : 0.0f;
        const float w10 = (vx0 && vy1) ? (wx0 * wy1) : 0.0f;
        const float w11 = (vx1 && vy1) ? (wx1 * wy1) : 0.0f;

        s_off[tid] = make_int4((cy0 * Wv + cx0) * Cv,
                               (cy0 * Wv + cx1) * Cv,
                               (cy1 * Wv + cx0) * Cv,
                               (cy1 * Wv + cx1) * Cv);
        s_wgt[tid] = make_uint4(h2_as_u32(__float2half2_rn(w00)),
                                h2_as_u32(__float2half2_rn(w01)),
                                h2_as_u32(__float2half2_rn(w10)),
                                h2_as_u32(__float2half2_rn(w11)));
    }
    __syncthreads();

    // ---- Phase 2: gather + correlate ----
    const int lane = tid & 31;
    const int p = tid >> 5;                  // 0..15 pixel in tile (warp = pixel)
    const int w = w0 + p;
    const int pix = h0 * Wv + w;

    float Lf[8];
    {
        const float4* lp = (const float4*)&s_left[p * LPITCH + lane * 8];
        float4 A = lp[0], B = lp[1];
        Lf[0] = A.x; Lf[1] = A.y; Lf[2] = A.z; Lf[3] = A.w;
        Lf[4] = B.x; Lf[5] = B.y; Lf[6] = B.z; Lf[7] = B.w;
    }

    const __half* rbase = g_right_nhwc + (size_t)b * HW * Cv + lane * 8;

#pragma unroll
    for (int k = 0; k < Kv; k++) {
        const int4 off = s_off[p * Kv + k];
        const uint4 wg = s_wgt[p * Kv + k];
        const __half2 w00 = u32_as_h2(wg.x);
        const __half2 w01 = u32_as_h2(wg.y);
        const __half2 w10 = u32_as_h2(wg.z);
        const __half2 w11 = u32_as_h2(wg.w);

        const uint4 g00 = *reinterpret_cast<const uint4*>(rbase + off.x);
        const uint4 g01 = *reinterpret_cast<const uint4*>(rbase + off.y);
        const uint4 g10 = *reinterpret_cast<const uint4*>(rbase + off.z);
        const uint4 g11 = *reinterpret_cast<const uint4*>(rbase + off.w);

        const __half2* pa = (const __half2*)&g00;
        const __half2* pc = (const __half2*)&g01;
        const __half2* pd = (const __half2*)&g10;
        const __half2* pe = (const __half2*)&g11;

        float s0 = 0.0f, s1 = 0.0f;
#pragma unroll
        for (int j = 0; j < 4; j++) {
            __half2 v = __hmul2(w00, pa[j]);
            v = __hfma2(w01, pc[j], v);
            v = __hfma2(w10, pd[j], v);
            v = __hfma2(w11, pe[j], v);
            float2 f = __half22float2(v);
            s0 = fmaf(Lf[2 * j], f.x, s0);
            s1 = fmaf(Lf[2 * j + 1], f.y, s1);
        }
        float s = s0 + s1;

        // reduce across the 8 threads of this channel-group (contiguous lanes)
        s += __shfl_xor_sync(0xffffffffu, s, 4);
        s += __shfl_xor_sync(0xffffffffu, s, 2);
        s += __shfl_xor_sync(0xffffffffu, s, 1);

        if ((lane & 7) == 0) {
            const int g = lane >> 3;  // 0..3
            out[((size_t)(b * Gv + g) * Kv + k) * HW + pix] = s * (1.0f / GC);
        }
    }
}

extern "C" void kernel_launch(void* const* d_in, const int* in_sizes, int n_in,
                              void* d_out, int out_size) {
    const float* left  = (const float*)d_in[0];
    const float* right = (const float*)d_in[1];
    const float* flow  = (const float*)d_in[2];
    const float* extra = (const float*)d_in[3];
    float* out = (float*)d_out;

    {
        dim3 grid(Wv / 32, Cv / 64, Bv * Hv);
        nchw_to_nhwc_half_kernel<<<grid, 256>>>(right);
    }
    {
        dim3 grid(Wv / TPX, Hv, Bv);
        corr_kernel<<<grid, 512>>>(left, flow, extra, out);
    }
}